// round 6
// baseline (speedup 1.0000x reference)
#include <cuda_runtime.h>

typedef unsigned long long U64;

// ---------------- packed f32x2 helpers (Blackwell FFMA2, PTX-only) ----------------
__device__ __forceinline__ U64 pk2(float x, float y) {
    U64 r; asm("mov.b64 %0, {%1, %2};" : "=l"(r) : "f"(x), "f"(y)); return r;
}
__device__ __forceinline__ float lo2(U64 v) {
    float x; asm("{ .reg .f32 hi; mov.b64 {%0, hi}, %1; }" : "=f"(x) : "l"(v)); return x;
}
__device__ __forceinline__ float hi2(U64 v) {
    float y; asm("{ .reg .f32 lo; mov.b64 {lo, %0}, %1; }" : "=f"(y) : "l"(v)); return y;
}
__device__ __forceinline__ U64 fma2(U64 a, U64 b, U64 c) {
    U64 d; asm("fma.rn.f32x2 %0, %1, %2, %3;" : "=l"(d) : "l"(a), "l"(b), "l"(c)); return d;
}
__device__ __forceinline__ U64 add2(U64 a, U64 b) {
    U64 d; asm("add.rn.f32x2 %0, %1, %2;" : "=l"(d) : "l"(a), "l"(b)); return d;
}

// ---------------- fast transcendentals ----------------
__device__ __forceinline__ float rsqf(float x) { float r; asm("rsqrt.approx.f32 %0, %1;" : "=f"(r) : "f"(x)); return r; }
__device__ __forceinline__ float tanh_ap(float x) { float r; asm("tanh.approx.f32 %0, %1;" : "=f"(r) : "f"(x)); return r; }
__device__ __forceinline__ float sigm_ap(float v) {
    return fmaf(tanh_ap(0.5f * v), 0.5f, 0.5f);
}

static constexpr int Tn = 1000;
static constexpr int In = 13;
static constexpr int Hn = 13;
static constexpr int Bn = 2048;
static constexpr long long OUT_ELEMS = (long long)Bn * Tn * 2 * Hn;  // 53,248,000
static constexpr long long HN_ELEMS  = 2LL * Bn * Hn;

// Scratch: gate preactivation float4 (i,f,g,o) laid out [dir][b][t][k].  852 MB.
__device__ float4 g_pre[2LL * Bn * Tn * Hn];

// =====================================================================
// Kernel A: x-path, one THREAD per (b,t). LayerNorm folded into weights:
//   y = rs*(W'.x - mu*u) + v.  Unchanged from R5 (memory-bound ~284us).
// =====================================================================
__global__ void __launch_bounds__(128, 3) xpre_kernel(
    const float* __restrict__ x,
    const float* __restrict__ ln_w, const float* __restrict__ ln_b,
    const float* __restrict__ wih_f, const float* __restrict__ bih_f, const float* __restrict__ bhh_f,
    const float* __restrict__ wih_b, const float* __restrict__ bih_b, const float* __restrict__ bhh_b)
{
    __shared__ __align__(16) float4 ssm[128 * 13];     // 26,624 B staging
    __shared__ __align__(8)  float wsm[13][52][2];     // folded weights, both dirs
    __shared__ __align__(8)  float usm[52][2];
    __shared__ __align__(8)  float vsm[52][2];

    const int tid = threadIdx.x;

    if (tid < 104) {
        const int dir = tid / 52;
        const int r   = tid % 52;
        const float* W  = dir ? wih_b : wih_f;
        const float* Bi = dir ? bih_b : bih_f;
        const float* Bh = dir ? bhh_b : bhh_f;
        float u = 0.0f;
        float v = __ldg(&Bi[r]) + __ldg(&Bh[r]);
#pragma unroll
        for (int j = 0; j < In; ++j) {
            const float wv = __ldg(&W[r * In + j]);
            const float wp = wv * __ldg(&ln_w[j]);
            wsm[j][tid >> 1][tid & 1] = wp;
            u += wp;
            v = fmaf(wv, __ldg(&ln_b[j]), v);
        }
        usm[tid >> 1][tid & 1] = u;
        vsm[tid >> 1][tid & 1] = v;
    }
    __syncthreads();

    const int b  = blockIdx.y;
    const int t0 = blockIdx.x * 128;
    const int t  = t0 + tid;
    const bool act = (t < Tn);
    const int nvalid = (Tn - t0 < 128) ? (Tn - t0) : 128;

    float xv[In];
    float S = 0.0f, S2 = 0.0f;
    const float* xp = x + ((long long)b * Tn + t) * In;
#pragma unroll
    for (int j = 0; j < In; ++j) {
        xv[j] = act ? __ldg(xp + j) : 0.0f;
        S += xv[j];
        S2 = fmaf(xv[j], xv[j], S2);
    }
    const float mu  = S * (1.0f / 13.0f);
    const float var = fmaf(-mu, mu, S2 * (1.0f / 13.0f));
    const float rs  = rsqf(var + 1e-5f);
    const U64 nmu2 = pk2(-mu, -mu);
    const U64 rs2  = pk2(rs, rs);

#pragma unroll
    for (int d = 0; d < 2; ++d) {
        U64 acc[26];
#pragma unroll
        for (int p = 0; p < 26; ++p) acc[p] = 0ULL;

        for (int j = 0; j < In; ++j) {
            const U64 xj2 = pk2(xv[j], xv[j]);
#pragma unroll
            for (int p = 0; p < 26; ++p)
                acc[p] = fma2(*(const U64*)&wsm[j][d * 26 + p][0], xj2, acc[p]);
        }

        float row[52];
#pragma unroll
        for (int p = 0; p < 26; ++p) {
            const U64 tmp = fma2(*(const U64*)&usm[d * 26 + p][0], nmu2, acc[p]);
            const U64 y   = fma2(tmp, rs2, *(const U64*)&vsm[d * 26 + p][0]);
            row[2 * p]     = lo2(y);
            row[2 * p + 1] = hi2(y);
        }

#pragma unroll
        for (int k = 0; k < Hn; ++k)
            ssm[tid * 13 + k] = make_float4(row[k], row[Hn + k], row[2 * Hn + k], row[3 * Hn + k]);
        __syncthreads();

        float4* dst = g_pre + ((long long)d * Bn * Tn + (long long)b * Tn + t0) * Hn;
        const int n = nvalid * 13;
        for (int i = tid; i < n; i += 128)
            dst[i] = ssm[i];
        __syncthreads();
    }
}

// =====================================================================
// Kernel B: recurrence. One warp per batch row; lanes 0-15 fwd, 16-31 bwd.
// h stored as duplicated pairs packed 2-per-float4 so the matvec consumes
// 7 LDS.128 (was 13 LDS.64): halves L1tex wavefronts + issue slots.
// Slot 13 padded (h=0, w=0) -> uniform 7-iteration loop, 28 fma2 dual-acc.
// 4-deep LDG prefetch pipeline; tanh.approx activations.
// =====================================================================
__global__ void __launch_bounds__(64, 7) rec_kernel(
    const float* __restrict__ whh_f, const float* __restrict__ whh_b,
    float* __restrict__ out)
{
    // [warp][buf][dir][7 float4]: float4 p holds (h_{2p},h_{2p},h_{2p+1},h_{2p+1})
    __shared__ __align__(16) float4 hsm[2][2][2][7];

    const int lane = threadIdx.x & 31;
    const int w    = threadIdx.x >> 5;
    const int dir  = lane >> 4;
    const int k    = lane & 15;
    const bool active = (k < Hn);
    const int kk   = active ? k : 0;
    const int b    = blockIdx.x * 2 + w;

    const float* Whh = dir ? whh_b : whh_f;

    // Row pairs, index j=0..13 with j=13 zero-padded
    U64 wif[14], wgo[14];
#pragma unroll
    for (int j = 0; j < In; ++j) {
        wif[j] = pk2(__ldg(&Whh[kk * Hn + j]),            __ldg(&Whh[(Hn + kk) * Hn + j]));
        wgo[j] = pk2(__ldg(&Whh[(2 * Hn + kk) * Hn + j]), __ldg(&Whh[(3 * Hn + kk) * Hn + j]));
    }
    wif[13] = 0ULL;
    wgo[13] = 0ULL;

    // zero both buffers fully (lanes cover 2 dirs x 16 slots > 2x7 float4)
    {
        float2* z0 = (float2*)&hsm[w][0][0][0];
        float2* z1 = (float2*)&hsm[w][1][0][0];
        if (lane < 28) { z0[lane] = make_float2(0.f, 0.f); z1[lane] = make_float2(0.f, 0.f); }
    }
    __syncwarp();

    // g_pre layout [dir][b][t][k]
    const float4* gp = g_pre + ((long long)dir * Bn * Tn + (long long)b * Tn
                                + (dir ? Tn - 1 : 0)) * Hn + kk;
    const int dgp = dir ? -Hn : Hn;

    float* op = out + (long long)b * (Tn * 2 * Hn)
                    + (dir ? (long long)(Tn - 1) * 2 * Hn : 0) + dir * Hn + kk;
    const int dop = dir ? -(2 * Hn) : (2 * Hn);

    float c = 0.0f, h = 0.0f;

    float4 gb[4];
#pragma unroll
    for (int i = 0; i < 4; ++i) { gb[i] = __ldg(gp); gp += dgp; }

#pragma unroll 2
    for (int t = 0; t < Tn; ++t) {
        const float4 g = gb[t & 3];
        if (t + 4 < Tn) { gb[t & 3] = __ldg(gp); gp += dgp; }

        const int cur = t & 1, nxt = cur ^ 1;

        U64 aif0 = pk2(g.x, g.y), aif1 = 0ULL;
        U64 ago0 = pk2(g.z, g.w), ago1 = 0ULL;
#pragma unroll
        for (int p = 0; p < 7; ++p) {
            const float4 hq = hsm[w][cur][dir][p];   // LDS.128 broadcast
            const U64 h0 = pk2(hq.x, hq.y);          // register-pair aliasing: no-op movs
            const U64 h1 = pk2(hq.z, hq.w);
            aif0 = fma2(wif[2 * p],     h0, aif0);
            ago0 = fma2(wgo[2 * p],     h0, ago0);
            aif1 = fma2(wif[2 * p + 1], h1, aif1);
            ago1 = fma2(wgo[2 * p + 1], h1, ago1);
        }
        const U64 aif = add2(aif0, aif1);
        const U64 ago = add2(ago0, ago1);

        const float gi = sigm_ap(lo2(aif));
        const float gf = sigm_ap(hi2(aif));
        const float gg = tanh_ap(lo2(ago));
        const float go = sigm_ap(hi2(ago));

        c = fmaf(gf, c, gi * gg);
        h = go * tanh_ap(c);

        if (active) {
            ((float2*)&hsm[w][nxt][dir][0])[k] = make_float2(h, h);
            *op = h;
        }
        op += dop;
        __syncwarp();
    }

    if (active) {
        float* hn = out + OUT_ELEMS + (long long)dir * (Bn * Hn) + (long long)b * Hn + k;
        hn[0] = h;
        hn[HN_ELEMS] = c;
    }
}

extern "C" void kernel_launch(void* const* d_in, const int* in_sizes, int n_in,
                              void* d_out, int out_size)
{
    const float* x     = (const float*)d_in[0];
    const float* ln_w  = (const float*)d_in[1];
    const float* ln_b  = (const float*)d_in[2];
    const float* wih_f = (const float*)d_in[3];
    const float* whh_f = (const float*)d_in[4];
    const float* bih_f = (const float*)d_in[5];
    const float* bhh_f = (const float*)d_in[6];
    const float* wih_b = (const float*)d_in[7];
    const float* whh_b = (const float*)d_in[8];
    const float* bih_b = (const float*)d_in[9];
    const float* bhh_b = (const float*)d_in[10];
    float* out = (float*)d_out;

    dim3 gridA((Tn + 127) / 128, Bn);
    xpre_kernel<<<gridA, 128>>>(x, ln_w, ln_b,
                                wih_f, bih_f, bhh_f,
                                wih_b, bih_b, bhh_b);

    rec_kernel<<<Bn / 2, 64>>>(whh_f, whh_b, out);
}

// round 8
// speedup vs baseline: 1.8275x; 1.8275x over previous
#include <cuda_runtime.h>
#include <cuda_fp16.h>

typedef unsigned long long U64;

// ---------------- packed f32x2 helpers (Blackwell FFMA2, PTX-only) ----------------
__device__ __forceinline__ U64 pk2(float x, float y) {
    U64 r; asm("mov.b64 %0, {%1, %2};" : "=l"(r) : "f"(x), "f"(y)); return r;
}
__device__ __forceinline__ float lo2(U64 v) {
    float x; asm("{ .reg .f32 hi; mov.b64 {%0, hi}, %1; }" : "=f"(x) : "l"(v)); return x;
}
__device__ __forceinline__ float hi2(U64 v) {
    float y; asm("{ .reg .f32 lo; mov.b64 {lo, %0}, %1; }" : "=f"(y) : "l"(v)); return y;
}
__device__ __forceinline__ U64 fma2(U64 a, U64 b, U64 c) {
    U64 d; asm("fma.rn.f32x2 %0, %1, %2, %3;" : "=l"(d) : "l"(a), "l"(b), "l"(c)); return d;
}
__device__ __forceinline__ U64 add2(U64 a, U64 b) {
    U64 d; asm("add.rn.f32x2 %0, %1, %2;" : "=l"(d) : "l"(a), "l"(b)); return d;
}

// ---------------- fast transcendentals ----------------
__device__ __forceinline__ float rsqf(float x) { float r; asm("rsqrt.approx.f32 %0, %1;" : "=f"(r) : "f"(x)); return r; }
__device__ __forceinline__ float tanh_ap(float x) { float r; asm("tanh.approx.f32 %0, %1;" : "=f"(r) : "f"(x)); return r; }
__device__ __forceinline__ float sigm_ap(float v) {
    return fmaf(tanh_ap(0.5f * v), 0.5f, 0.5f);
}

static constexpr int Tn = 1000;
static constexpr int In = 13;
static constexpr int Hn = 13;
static constexpr int Bn = 2048;
static constexpr long long OUT_ELEMS = (long long)Bn * Tn * 2 * Hn;  // 53,248,000
static constexpr long long HN_ELEMS  = 2LL * Bn * Hn;

// Scratch: gate preactivations (i,f,g,o) as half4 (one uint2 per (t,k)),
// laid out [dir][b][t][k].  426 MB (halved from fp32).
__device__ uint2 g_pre_h[2LL * Bn * Tn * Hn];

// =====================================================================
// Kernel A: x-path, one THREAD per (b,t). LayerNorm folded into weights:
//   y = rs*(W'.x - mu*u) + v.  Output converted to fp16 half4 and staged
//   in smem, then block-copied out with perfect linear coalescing.
// =====================================================================
__global__ void __launch_bounds__(128, 3) xpre_kernel(
    const float* __restrict__ x,
    const float* __restrict__ ln_w, const float* __restrict__ ln_b,
    const float* __restrict__ wih_f, const float* __restrict__ bih_f, const float* __restrict__ bhh_f,
    const float* __restrict__ wih_b, const float* __restrict__ bih_b, const float* __restrict__ bhh_b)
{
    __shared__ __align__(16) uint2 ssm[128 * 13];      // 13,312 B staging (half4)
    __shared__ __align__(8)  float wsm[13][52][2];     // folded weights, both dirs
    __shared__ __align__(8)  float usm[52][2];
    __shared__ __align__(8)  float vsm[52][2];

    const int tid = threadIdx.x;

    // Prologue: build folded-weight tables (104 rows over 104 threads)
    if (tid < 104) {
        const int dir = tid / 52;
        const int r   = tid % 52;
        const float* W  = dir ? wih_b : wih_f;
        const float* Bi = dir ? bih_b : bih_f;
        const float* Bh = dir ? bhh_b : bhh_f;
        float u = 0.0f;
        float v = __ldg(&Bi[r]) + __ldg(&Bh[r]);
#pragma unroll
        for (int j = 0; j < In; ++j) {
            const float wv = __ldg(&W[r * In + j]);
            const float wp = wv * __ldg(&ln_w[j]);
            wsm[j][tid >> 1][tid & 1] = wp;
            u += wp;
            v = fmaf(wv, __ldg(&ln_b[j]), v);
        }
        usm[tid >> 1][tid & 1] = u;
        vsm[tid >> 1][tid & 1] = v;
    }
    __syncthreads();

    const int b  = blockIdx.y;
    const int t0 = blockIdx.x * 128;
    const int t  = t0 + tid;
    const bool act = (t < Tn);
    const int nvalid = (Tn - t0 < 128) ? (Tn - t0) : 128;

    // Load x row; local LN stats (no reduction)
    float xv[In];
    float S = 0.0f, S2 = 0.0f;
    const float* xp = x + ((long long)b * Tn + t) * In;
#pragma unroll
    for (int j = 0; j < In; ++j) {
        xv[j] = act ? __ldg(xp + j) : 0.0f;
        S += xv[j];
        S2 = fmaf(xv[j], xv[j], S2);
    }
    const float mu  = S * (1.0f / 13.0f);
    const float var = fmaf(-mu, mu, S2 * (1.0f / 13.0f));
    const float rs  = rsqf(var + 1e-5f);
    const U64 nmu2 = pk2(-mu, -mu);
    const U64 rs2  = pk2(rs, rs);

#pragma unroll
    for (int d = 0; d < 2; ++d) {
        U64 acc[26];
#pragma unroll
        for (int p = 0; p < 26; ++p) acc[p] = 0ULL;

        for (int j = 0; j < In; ++j) {             // rolled: small I-footprint
            const U64 xj2 = pk2(xv[j], xv[j]);
#pragma unroll
            for (int p = 0; p < 26; ++p)
                acc[p] = fma2(*(const U64*)&wsm[j][d * 26 + p][0], xj2, acc[p]);
        }

        float row[52];
#pragma unroll
        for (int p = 0; p < 26; ++p) {
            const U64 tmp = fma2(*(const U64*)&usm[d * 26 + p][0], nmu2, acc[p]);
            const U64 y   = fma2(tmp, rs2, *(const U64*)&vsm[d * 26 + p][0]);
            row[2 * p]     = lo2(y);
            row[2 * p + 1] = hi2(y);
        }

        // Convert to half4 and stage (stride-13 uint2 rows)
#pragma unroll
        for (int k = 0; k < Hn; ++k) {
            const __half2 p01 = __float22half2_rn(make_float2(row[k],          row[Hn + k]));
            const __half2 p23 = __float22half2_rn(make_float2(row[2 * Hn + k], row[3 * Hn + k]));
            uint2 u2;
            u2.x = *(const unsigned*)&p01;
            u2.y = *(const unsigned*)&p23;
            ssm[tid * 13 + k] = u2;
        }
        __syncthreads();

        // Linear coalesced copy-out: smem index == dst index
        uint2* dst = g_pre_h + ((long long)d * Bn * Tn + (long long)b * Tn + t0) * Hn;
        const int n = nvalid * 13;
        for (int i = tid; i < n; i += 128)
            dst[i] = ssm[i];
        __syncthreads();   // before ssm reuse by d=1
    }
}

// =====================================================================
// Kernel B: recurrence (R5 known-good body). One warp per batch row;
// lanes 0-15 fwd, 16-31 bwd. 4-deep LDG.64 prefetch pipeline on fp16 gate
// preacts (converted to fp32 at consume, off the critical path). h stored
// DUPLICATED (h,h) in smem; dual accumulators; tanh.approx activations.
// =====================================================================
__global__ void __launch_bounds__(64, 7) rec_kernel(
    const float* __restrict__ whh_f, const float* __restrict__ whh_b,
    float* __restrict__ out)
{
    __shared__ __align__(8) float2 hsm[2][2][2][14];  // [warp][buf][dir][pad 14]

    const int lane = threadIdx.x & 31;
    const int w    = threadIdx.x >> 5;
    const int dir  = lane >> 4;
    const int k    = lane & 15;
    const bool active = (k < Hn);
    const int kk   = active ? k : 0;
    const int b    = blockIdx.x * 2 + w;

    const float* Whh = dir ? whh_b : whh_f;

    U64 wif[In], wgo[In];
#pragma unroll
    for (int j = 0; j < In; ++j) {
        wif[j] = pk2(__ldg(&Whh[kk * Hn + j]),            __ldg(&Whh[(Hn + kk) * Hn + j]));
        wgo[j] = pk2(__ldg(&Whh[(2 * Hn + kk) * Hn + j]), __ldg(&Whh[(3 * Hn + kk) * Hn + j]));
    }

    if (active) {
        hsm[w][0][dir][k] = make_float2(0.0f, 0.0f);
        hsm[w][1][dir][k] = make_float2(0.0f, 0.0f);
    }
    __syncwarp();

    // g_pre_h layout [dir][b][t][k]
    const uint2* gp = g_pre_h + ((long long)dir * Bn * Tn + (long long)b * Tn
                                 + (dir ? Tn - 1 : 0)) * Hn + kk;
    const int dgp = dir ? -Hn : Hn;

    float* op = out + (long long)b * (Tn * 2 * Hn)
                    + (dir ? (long long)(Tn - 1) * 2 * Hn : 0) + dir * Hn + kk;
    const int dop = dir ? -(2 * Hn) : (2 * Hn);

    float c = 0.0f, h = 0.0f;

    uint2 gb[4];
#pragma unroll
    for (int i = 0; i < 4; ++i) { gb[i] = __ldg(gp); gp += dgp; }

#pragma unroll 4
    for (int t = 0; t < Tn; ++t) {
        const uint2 graw = gb[t & 3];
        if (t + 4 < Tn) { gb[t & 3] = __ldg(gp); gp += dgp; }

        // fp16 -> fp32 (4 F2F, independent, hidden by pipeline)
        const float2 gxy = __half22float2(*(const __half2*)&graw.x);
        const float2 gzw = __half22float2(*(const __half2*)&graw.y);

        const int cur = t & 1, nxt = cur ^ 1;

        U64 aif0 = pk2(gxy.x, gxy.y), aif1 = 0ULL;
        U64 ago0 = pk2(gzw.x, gzw.y), ago1 = 0ULL;
#pragma unroll
        for (int j = 0; j < 12; j += 2) {
            const U64 h0 = *(const U64*)&hsm[w][cur][dir][j];
            const U64 h1 = *(const U64*)&hsm[w][cur][dir][j + 1];
            aif0 = fma2(wif[j],     h0, aif0);
            ago0 = fma2(wgo[j],     h0, ago0);
            aif1 = fma2(wif[j + 1], h1, aif1);
            ago1 = fma2(wgo[j + 1], h1, ago1);
        }
        {
            const U64 h12 = *(const U64*)&hsm[w][cur][dir][12];
            aif0 = fma2(wif[12], h12, aif0);
            ago0 = fma2(wgo[12], h12, ago0);
        }
        const U64 aif = add2(aif0, aif1);
        const U64 ago = add2(ago0, ago1);

        const float gi = sigm_ap(lo2(aif));
        const float gf = sigm_ap(hi2(aif));
        const float gg = tanh_ap(lo2(ago));
        const float go = sigm_ap(hi2(ago));

        c = fmaf(gf, c, gi * gg);
        h = go * tanh_ap(c);

        if (active) { hsm[w][nxt][dir][k] = make_float2(h, h); *op = h; }
        op += dop;
        __syncwarp();
    }

    if (active) {
        float* hn = out + OUT_ELEMS + (long long)dir * (Bn * Hn) + (long long)b * Hn + k;
        hn[0] = h;
        hn[HN_ELEMS] = c;
    }
}

extern "C" void kernel_launch(void* const* d_in, const int* in_sizes, int n_in,
                              void* d_out, int out_size)
{
    const float* x     = (const float*)d_in[0];
    const float* ln_w  = (const float*)d_in[1];
    const float* ln_b  = (const float*)d_in[2];
    const float* wih_f = (const float*)d_in[3];
    const float* whh_f = (const float*)d_in[4];
    const float* bih_f = (const float*)d_in[5];
    const float* bhh_f = (const float*)d_in[6];
    const float* wih_b = (const float*)d_in[7];
    const float* whh_b = (const float*)d_in[8];
    const float* bih_b = (const float*)d_in[9];
    const float* bhh_b = (const float*)d_in[10];
    float* out = (float*)d_out;

    dim3 gridA((Tn + 127) / 128, Bn);
    xpre_kernel<<<gridA, 128>>>(x, ln_w, ln_b,
                                wih_f, bih_f, bhh_f,
                                wih_b, bih_b, bhh_b);

    rec_kernel<<<Bn / 2, 64>>>(whh_f, whh_b, out);
}